// round 13
// baseline (speedup 1.0000x reference)
#include <cuda_runtime.h>
#include <cstdint>
#include <math_constants.h>

#define NKNOTS 64
#define DEG 3
#define NB 60
#define RBLK 128

#define Hf 0.01754385964912280702f  // 1/57
#define C6f 30865.5f                // 57^3/6
#define C4f 46298.25f               // 57^3/4
#define C1f 185193.0f               // 57^3

// ---------------- device scratch ----------------
__device__ float g_pmn[RBLK];
__device__ float g_pmx[RBLK];
__device__ int   g_arr = 0;   // arrival counter (reducer blocks)
__device__ int   g_fin = 0;   // finish counter (all blocks; last one resets)

// rare boundary column (true repeated-knot pieces; ~1e-5 of points)
__device__ __forceinline__ float rare_col(int i, int d, float xn,
                                          const float4* s_spec,
                                          const float* s_specc) {
    if (d > 3) {
        float t = (float)(i + 1) * Hf - xn;
        float c = (i >= 2) ? C6f : ((i == 1) ? C4f : C1f);
        return t * t * t * c;
    }
    if (d < 0) {
        float t = xn - (float)(i - 3) * Hf;
        float c = (i < 58) ? C6f : ((i == 58) ? C4f : C1f);
        return t * t * t * c;
    }
    int row = (i < 3) ? (i * 4 + d) : (12 + (i - 57) * 4 + d);
    float4 a = s_spec[row];
    float tt = xn - s_specc[row];
    return fmaf(fmaf(fmaf(a.w, tt, a.z), tt, a.y), tt, a.x);
}

// one column via the folded closed form:
//   d = 57*xn - i + 1;  q = 1 - |d|;  c = (q>0) ? -0.5 : 1/6
//   B = ((c*q + 0.5)*q + 0.5)*q + 1/6
__device__ __forceinline__ float col_eval(float d) {
    float q = fmaf(fabsf(d), -1.0f, 1.0f);
    float c = (q > 0.0f) ? -0.5f : 0.16666666666666666f;
    return fmaf(fmaf(fmaf(c, q, 0.5f), q, 0.5f), q, 0.16666666666666666f);
}

// ---------------- fused kernel: reduce + spin + main evaluation ----------
__global__ void __launch_bounds__(256, 8) k_fused(const float* __restrict__ x,
                                                  const float* __restrict__ knots,
                                                  float* __restrict__ out, int n) {
    __shared__ float4 s_spec[24];
    __shared__ float  s_specc[24];
    __shared__ float  s_red[16];
    __shared__ float  s_mn, s_inv;

    const int tid = threadIdx.x;
    const int bid = blockIdx.x;

    // --- fp32 symbolic de Boor for the 24 boundary-element rows (all blocks,
    //     independent of min/max -> overlaps the reduce/spin phase) ---
    if (tid >= 32 && tid < 56) {
        int row = tid - 32;
        int i = (row < 12) ? (row >> 2) : 57 + ((row - 12) >> 2);
        int e = 3 + (row & 3);
        float T[11];
        #pragma unroll
        for (int m = 0; m < 5; m++) T[3 + m] = __ldg(knots + i + m);
        T[0] = T[1] = T[2] = T[3] - 1.0f;
        T[8] = T[9] = T[10] = T[7] + 1.0f;
        float cc = T[e];
        float res[4][4];
        #pragma unroll
        for (int a = 0; a < 4; a++)
            #pragma unroll
            for (int b = 0; b < 4; b++) res[a][b] = 0.0f;
        res[0][0] = 1.0f;
        for (int j = 1; j <= DEG; j++) {
            float hh[3][4];
            for (int a = 0; a < j; a++)
                for (int b = 0; b < 4; b++) hh[a][b] = res[a][b];
            for (int b = 0; b < 4; b++) res[0][b] = 0.0f;
            for (int nn = 1; nn <= j; nn++) {
                float tb = T[e + nn];
                float ta = T[e + nn - j];
                float den = tb - ta;
                float w[4] = {0.0f, 0.0f, 0.0f, 0.0f};
                if (den != 0.0f) {
                    float rd = 1.0f / den;
                    for (int b = 0; b < 4; b++) w[b] = hh[nn - 1][b] * rd;
                }
                float A = tb - cc, B = cc - ta;
                float nres[4];
                for (int b = 0; b < 4; b++) {
                    float sh = (b > 0) ? w[b - 1] : 0.0f;
                    res[nn - 1][b] += A * w[b] - sh;
                    nres[b] = B * w[b] + sh;
                }
                for (int b = 0; b < 4; b++) res[nn][b] = nres[b];
            }
        }
        int oi = 2 * DEG - e;
        s_spec[row] = make_float4(res[oi][0], res[oi][1], res[oi][2], res[oi][3]);
        s_specc[row] = cc;
    }

    // --- phase 1: blocks [0, RBLK) compute min/max partials ---
    if (bid < RBLK) {
        int n4 = n >> 2;
        const float4* x4 = reinterpret_cast<const float4*>(x);
        int Sr = RBLK * 256;
        int gid = bid * 256 + tid;
        float mn = CUDART_INF_F, mx = -CUDART_INF_F;
        for (int base = gid; base < n4; base += 4 * Sr) {
            #pragma unroll
            for (int k = 0; k < 4; k++) {
                int i = base + k * Sr;
                if (i < n4) {
                    float4 v = x4[i];
                    mn = fminf(mn, fminf(fminf(v.x, v.y), fminf(v.z, v.w)));
                    mx = fmaxf(mx, fmaxf(fmaxf(v.x, v.y), fmaxf(v.z, v.w)));
                }
            }
        }
        if (bid == 0 && tid < (n & 3)) {
            float v = x[n4 * 4 + tid];
            mn = fminf(mn, v);
            mx = fmaxf(mx, v);
        }
        #pragma unroll
        for (int o = 16; o; o >>= 1) {
            mn = fminf(mn, __shfl_xor_sync(0xFFFFFFFFu, mn, o));
            mx = fmaxf(mx, __shfl_xor_sync(0xFFFFFFFFu, mx, o));
        }
        __shared__ float smn[8], smx[8];
        int wid = tid >> 5, lid = tid & 31;
        if (lid == 0) { smn[wid] = mn; smx[wid] = mx; }
        __syncthreads();
        if (tid == 0) {
            #pragma unroll
            for (int w = 1; w < 8; w++) {
                mn = fminf(mn, smn[w]);
                mx = fmaxf(mx, smx[w]);
            }
            g_pmn[bid] = mn;
            g_pmx[bid] = mx;
            __threadfence();
            atomicAdd(&g_arr, 1);
        }
    }

    // --- phase 2: wait for all partials (thread 0 polls; others idle at bar) ---
    if (tid == 0) {
        while (*((volatile int*)&g_arr) < RBLK) __nanosleep(64);
        __threadfence();   // acquire: order partial reads after the flag
    }
    __syncthreads();

    // --- final reduce of the RBLK partials ---
    if (tid < RBLK) {
        float mn = g_pmn[tid];
        float mx = g_pmx[tid];
        #pragma unroll
        for (int o = 16; o; o >>= 1) {
            mn = fminf(mn, __shfl_xor_sync(0xFFFFFFFFu, mn, o));
            mx = fmaxf(mx, __shfl_xor_sync(0xFFFFFFFFu, mx, o));
        }
        if ((tid & 31) == 0) { s_red[tid >> 5] = mn; s_red[8 + (tid >> 5)] = mx; }
    }
    __syncthreads();
    if (tid == 0) {
        float mn = s_red[0], mx = s_red[8];
        #pragma unroll
        for (int w = 1; w < 4; w++) {
            mn = fminf(mn, s_red[w]);
            mx = fmaxf(mx, s_red[8 + w]);
        }
        s_mn = mn;
        s_inv = 1.0f / ((mx - mn) + 1e-8f);
    }
    __syncthreads();

    // --- phase 3: main evaluation (identical to R12) ---
    const float a_s = s_inv;
    const float b_s = -s_mn * s_inv;
    const int total = n << 4;
    const int S = gridDim.x * blockDim.x;        // 303104, divisible by 16
    float4* out4 = reinterpret_cast<float4*>(out);

    const int item0 = bid * blockDim.x + tid;
    const int g = item0 & 15;                    // loop-invariant per lane
    const bool g0 = (g == 0), g14 = (g == 14), gv = (g < 15);

    // fused: d0 = xv*a2 + b2  (== 57*xn + 1 - 4g)
    const float a2 = 57.0f * a_s;
    const float b2 = fmaf(57.0f, b_s, (float)(1 - (g << 2)));

    const int dp = S >> 4;                       // pid stride per S items
    int pid  = item0 >> 4;
    int slot = item0 - pid;                      // == pid*15 + g
    const int pmax = n - 1;

    auto eval = [&](float xv, float4& o) {
        float d0 = fmaf(xv, a2, b2);
        o.x = col_eval(d0);
        o.y = col_eval(d0 - 1.0f);
        o.z = col_eval(d0 - 2.0f);
        o.w = col_eval(d0 - 3.0f);
        if (g0) {
            if (d0 >= 4.0f) {               // common: i=0,1 extrapolated right
                o.x *= 6.0f;
                o.y *= 1.5f;
            } else {                        // xn < 3/57 — ultra-rare
                float xn = fmaf(xv, a_s, b_s);
                int P = 4 + min(56, max(0, (int)(xn * 57.0f)));
                o.x = rare_col(0, P - 1, xn, s_spec, s_specc);
                o.y = rare_col(1, P - 2, xn, s_spec, s_specc);
                o.z = rare_col(2, P - 3, xn, s_spec, s_specc);
            }
        } else if (g14) {
            if (d0 < 7.0f) {
                o.z *= 1.5f;
                o.w *= 6.0f;
            } else {
                float xn = fmaf(xv, a_s, b_s);
                int P = 4 + min(56, max(0, (int)(xn * 57.0f)));
                o.y = rare_col(57, P - 58, xn, s_spec, s_specc);
                o.z = rare_col(58, P - 59, xn, s_spec, s_specc);
                o.w = rare_col(59, P - 60, xn, s_spec, s_specc);
            }
        }
    };

    // software-pipelined, unrolled-by-2 grid-stride loop (clamped prefetch)
    int item = item0;
    float xa = __ldg(x + min(pid, pmax));
    float xb = __ldg(x + min(pid + dp, pmax));
    for (; item + S < total; item += 2 * S) {
        float cxa = xa, cxb = xb;
        xa = __ldg(x + min(pid + 2 * dp, pmax));   // prefetch next pair
        xb = __ldg(x + min(pid + 3 * dp, pmax));
        float4 oa, ob;
        eval(cxa, oa);
        eval(cxb, ob);
        if (gv) {
            __stcs(&out4[slot], oa);
            __stcs(&out4[slot + S - dp], ob);
        }
        pid += 2 * dp;
        slot += 2 * (S - dp);
    }
    if (item < total) {
        float4 oa;
        eval(xa, oa);
        if (gv) __stcs(&out4[slot], oa);
    }

    // --- epilogue: last-finishing block resets counters for the next replay ---
    __syncthreads();
    if (tid == 0) {
        int old = atomicAdd(&g_fin, 1);
        if (old == gridDim.x - 1) {
            g_arr = 0;
            g_fin = 0;
            __threadfence();
        }
    }
}

// ---------------- launch ----------------
extern "C" void kernel_launch(void* const* d_in, const int* in_sizes, int n_in,
                              void* d_out, int out_size) {
    const float* x = (const float*)d_in[0];
    const float* knots = (const float*)d_in[1];
    int n = in_sizes[0];

    k_fused<<<1184, 256>>>(x, knots, (float*)d_out, n);
}

// round 14
// speedup vs baseline: 1.0767x; 1.0767x over previous
#include <cuda_runtime.h>
#include <cstdint>
#include <math_constants.h>

#define NKNOTS 64
#define DEG 3
#define NB 60
#define RBLK 128

#define Hf 0.01754385964912280702f  // 1/57
#define C6f 30865.5f                // 57^3/6
#define C4f 46298.25f               // 57^3/4
#define C1f 185193.0f               // 57^3

// ---------------- device scratch ----------------
__device__ float g_pmn[RBLK];
__device__ float g_pmx[RBLK];

// ---------------- kernel 1: per-block min/max partials (MLP=4) ----------
__global__ void __launch_bounds__(256) k_reduce(const float* __restrict__ x, int n) {
    int n4 = n >> 2;
    const float4* x4 = reinterpret_cast<const float4*>(x);
    int S = gridDim.x * blockDim.x;
    int gid = blockIdx.x * blockDim.x + threadIdx.x;
    float mn = CUDART_INF_F, mx = -CUDART_INF_F;
    for (int base = gid; base < n4; base += 4 * S) {
        #pragma unroll
        for (int k = 0; k < 4; k++) {
            int i = base + k * S;
            if (i < n4) {
                float4 v = x4[i];
                mn = fminf(mn, fminf(fminf(v.x, v.y), fminf(v.z, v.w)));
                mx = fmaxf(mx, fmaxf(fmaxf(v.x, v.y), fmaxf(v.z, v.w)));
            }
        }
    }
    if (blockIdx.x == 0 && threadIdx.x < (n & 3)) {
        float v = x[n4 * 4 + threadIdx.x];
        mn = fminf(mn, v);
        mx = fmaxf(mx, v);
    }
    #pragma unroll
    for (int o = 16; o; o >>= 1) {
        mn = fminf(mn, __shfl_xor_sync(0xFFFFFFFFu, mn, o));
        mx = fmaxf(mx, __shfl_xor_sync(0xFFFFFFFFu, mx, o));
    }
    __shared__ float smn[8], smx[8];
    int wid = threadIdx.x >> 5, lid = threadIdx.x & 31;
    if (lid == 0) { smn[wid] = mn; smx[wid] = mx; }
    __syncthreads();
    if (threadIdx.x == 0) {
        #pragma unroll
        for (int w = 1; w < 8; w++) {
            mn = fminf(mn, smn[w]);
            mx = fmaxf(mx, smx[w]);
        }
        g_pmn[blockIdx.x] = mn;
        g_pmx[blockIdx.x] = mx;
    }
}

// rare boundary column (true repeated-knot pieces; ~1e-5 of points)
__device__ __forceinline__ float rare_col(int i, int d, float xn,
                                          const float4* s_spec,
                                          const float* s_specc) {
    if (d > 3) {
        float t = (float)(i + 1) * Hf - xn;
        float c = (i >= 2) ? C6f : ((i == 1) ? C4f : C1f);
        return t * t * t * c;
    }
    if (d < 0) {
        float t = xn - (float)(i - 3) * Hf;
        float c = (i < 58) ? C6f : ((i == 58) ? C4f : C1f);
        return t * t * t * c;
    }
    int row = (i < 3) ? (i * 4 + d) : (12 + (i - 57) * 4 + d);
    float4 a = s_spec[row];
    float tt = xn - s_specc[row];
    return fmaf(fmaf(fmaf(a.w, tt, a.z), tt, a.y), tt, a.x);
}

// one column via the folded closed form:
//   d = 57*xn - i + 1;  q = 1 - |d|;  c = (q>0) ? -0.5 : 1/6
//   B = ((c*q + 0.5)*q + 0.5)*q + 1/6
__device__ __forceinline__ float col_eval(float d) {
    float q = fmaf(fabsf(d), -1.0f, 1.0f);
    float c = (q > 0.0f) ? -0.5f : 0.16666666666666666f;
    return fmaf(fmaf(fmaf(c, q, 0.5f), q, 0.5f), q, 0.16666666666666666f);
}

// ---------------- kernel 2: main evaluation (PDL secondary) ----------------
// Launched with programmatic stream serialization: starts while k_reduce is
// still running, computes the boundary table + issues the first x prefetches,
// then cudaGridDependencySynchronize() before consuming the partials.
__global__ void __launch_bounds__(256) k_main(const float* __restrict__ x,
                                              const float* __restrict__ knots,
                                              float* __restrict__ out, int n) {
    __shared__ float4 s_spec[24];
    __shared__ float  s_specc[24];
    __shared__ float  s_red[16];
    __shared__ float  s_mn, s_inv;

    int tid = threadIdx.x;

    // --- fp32 symbolic de Boor for the 24 boundary-element rows (pre-sync) ---
    if (tid >= 32 && tid < 56) {
        int row = tid - 32;
        int i = (row < 12) ? (row >> 2) : 57 + ((row - 12) >> 2);
        int e = 3 + (row & 3);
        float T[11];
        #pragma unroll
        for (int m = 0; m < 5; m++) T[3 + m] = __ldg(knots + i + m);
        T[0] = T[1] = T[2] = T[3] - 1.0f;
        T[8] = T[9] = T[10] = T[7] + 1.0f;
        float cc = T[e];
        float res[4][4];
        #pragma unroll
        for (int a = 0; a < 4; a++)
            #pragma unroll
            for (int b = 0; b < 4; b++) res[a][b] = 0.0f;
        res[0][0] = 1.0f;
        for (int j = 1; j <= DEG; j++) {
            float hh[3][4];
            for (int a = 0; a < j; a++)
                for (int b = 0; b < 4; b++) hh[a][b] = res[a][b];
            for (int b = 0; b < 4; b++) res[0][b] = 0.0f;
            for (int nn = 1; nn <= j; nn++) {
                float tb = T[e + nn];
                float ta = T[e + nn - j];
                float den = tb - ta;
                float w[4] = {0.0f, 0.0f, 0.0f, 0.0f};
                if (den != 0.0f) {
                    float rd = 1.0f / den;
                    for (int b = 0; b < 4; b++) w[b] = hh[nn - 1][b] * rd;
                }
                float A = tb - cc, B = cc - ta;
                float nres[4];
                for (int b = 0; b < 4; b++) {
                    float sh = (b > 0) ? w[b - 1] : 0.0f;
                    res[nn - 1][b] += A * w[b] - sh;
                    nres[b] = B * w[b] + sh;
                }
                for (int b = 0; b < 4; b++) res[nn][b] = nres[b];
            }
        }
        int oi = 2 * DEG - e;
        s_spec[row] = make_float4(res[oi][0], res[oi][1], res[oi][2], res[oi][3]);
        s_specc[row] = cc;
    }

    // --- pre-sync: set up indices and issue the first x prefetches ---
    const int total = n << 4;
    const int S = gridDim.x * blockDim.x;        // 303104, divisible by 16
    const int item0 = blockIdx.x * blockDim.x + tid;
    const int g = item0 & 15;                    // loop-invariant per lane
    const bool g0 = (g == 0), g14 = (g == 14), gv = (g < 15);
    const int dp = S >> 4;
    int pid  = item0 >> 4;
    int slot = item0 - pid;                      // == pid*15 + g
    const int pmax = n - 1;

    float xa = __ldg(x + min(pid, pmax));        // in flight across the sync
    float xb = __ldg(x + min(pid + dp, pmax));

    // --- wait for k_reduce's partials to be visible ---
    cudaGridDependencySynchronize();

    // --- final reduce of the RBLK partials ---
    if (tid < RBLK) {
        float mn = g_pmn[tid];
        float mx = g_pmx[tid];
        #pragma unroll
        for (int o = 16; o; o >>= 1) {
            mn = fminf(mn, __shfl_xor_sync(0xFFFFFFFFu, mn, o));
            mx = fmaxf(mx, __shfl_xor_sync(0xFFFFFFFFu, mx, o));
        }
        if ((tid & 31) == 0) { s_red[tid >> 5] = mn; s_red[8 + (tid >> 5)] = mx; }
    }
    __syncthreads();
    if (tid == 0) {
        float mn = s_red[0], mx = s_red[8];
        #pragma unroll
        for (int w = 1; w < 4; w++) {
            mn = fminf(mn, s_red[w]);
            mx = fmaxf(mx, s_red[8 + w]);
        }
        s_mn = mn;
        s_inv = 1.0f / ((mx - mn) + 1e-8f);
    }
    __syncthreads();

    const float a_s = s_inv;
    const float b_s = -s_mn * s_inv;
    float4* out4 = reinterpret_cast<float4*>(out);

    // fused: d0 = xv*a2 + b2  (== 57*xn + 1 - 4g)
    const float a2 = 57.0f * a_s;
    const float b2 = fmaf(57.0f, b_s, (float)(1 - (g << 2)));

    auto eval = [&](float xv, float4& o) {
        float d0 = fmaf(xv, a2, b2);
        o.x = col_eval(d0);
        o.y = col_eval(d0 - 1.0f);
        o.z = col_eval(d0 - 2.0f);
        o.w = col_eval(d0 - 3.0f);
        if (g0) {
            if (d0 >= 4.0f) {               // common: i=0,1 extrapolated right
                o.x *= 6.0f;
                o.y *= 1.5f;
            } else {                        // xn < 3/57 — ultra-rare
                float xn = fmaf(xv, a_s, b_s);
                int P = 4 + min(56, max(0, (int)(xn * 57.0f)));
                o.x = rare_col(0, P - 1, xn, s_spec, s_specc);
                o.y = rare_col(1, P - 2, xn, s_spec, s_specc);
                o.z = rare_col(2, P - 3, xn, s_spec, s_specc);
            }
        } else if (g14) {
            // d0 = 57*xn - 55; left-extrapolated iff xn < 54/57 <=> d0 < -1
            if (d0 < -1.0f) {
                o.z *= 1.5f;
                o.w *= 6.0f;
            } else {                        // xn >= 54/57 — ultra-rare
                float xn = fmaf(xv, a_s, b_s);
                int P = 4 + min(56, max(0, (int)(xn * 57.0f)));
                o.y = rare_col(57, P - 58, xn, s_spec, s_specc);
                o.z = rare_col(58, P - 59, xn, s_spec, s_specc);
                o.w = rare_col(59, P - 60, xn, s_spec, s_specc);
            }
        }
    };

    // software-pipelined, unrolled-by-2 grid-stride loop (clamped prefetch)
    int item = item0;
    for (; item + S < total; item += 2 * S) {
        float cxa = xa, cxb = xb;
        xa = __ldg(x + min(pid + 2 * dp, pmax));   // prefetch next pair
        xb = __ldg(x + min(pid + 3 * dp, pmax));
        float4 oa, ob;
        eval(cxa, oa);
        eval(cxb, ob);
        if (gv) {
            __stcs(&out4[slot], oa);
            __stcs(&out4[slot + S - dp], ob);
        }
        pid += 2 * dp;
        slot += 2 * (S - dp);
    }
    if (item < total) {
        float4 oa;
        eval(xa, oa);
        if (gv) __stcs(&out4[slot], oa);
    }
}

// ---------------- launch ----------------
extern "C" void kernel_launch(void* const* d_in, const int* in_sizes, int n_in,
                              void* d_out, int out_size) {
    const float* x = (const float*)d_in[0];
    const float* knots = (const float*)d_in[1];
    int n = in_sizes[0];

    k_reduce<<<RBLK, 256>>>(x, n);

    // PDL: k_main may start before k_reduce completes; its pre-sync phase
    // (boundary table + first prefetches) overlaps the reduction.
    cudaLaunchAttribute attr[1];
    attr[0].id = cudaLaunchAttributeProgrammaticStreamSerialization;
    attr[0].val.programmaticStreamSerializationAllowed = 1;
    cudaLaunchConfig_t cfg = {};
    cfg.gridDim = dim3(1184);
    cfg.blockDim = dim3(256);
    cfg.dynamicSmemBytes = 0;
    cfg.stream = 0;
    cfg.attrs = attr;
    cfg.numAttrs = 1;
    cudaLaunchKernelEx(&cfg, k_main, x, knots, (float*)d_out, n);
}